// round 2
// baseline (speedup 1.0000x reference)
#include <cuda_runtime.h>

// crazyleg: batched 2-link leg dynamics. B = 1e6 rows.
// Inputs : q (B,2), q_dot (B,2), A (B,7), U (B,7)  -- all float32
// Outputs (flattened, concatenated): Gq (B,2), Cmat (B,2,2), Mmat (B,2,2),
//   Rmat (B,2,7), L (B,7), Adot (B,7)  => 38*B floats
//
// Strategy: HBM-bound elementwise kernel. All accesses coalesced:
//  - Gq/Cmat/Mmat: direct float2/float4 vector stores (aligned by construction)
//  - Rmat/L: staged in shared memory in their exact flat gmem layout, then
//    written stride-1 coalesced
//  - Adot: flat float4 stream over 7*B elements (independent of row structure)

#define PI_2f 1.57079632679489662f
#define BLOCK 128

__device__ __forceinline__ float blend(float L) {
    // s = 0.95 * sigmoid(100*(L-0.07));  L*s + (1-s)*0.05
    float s = 0.95f / (1.0f + __expf(-100.0f * (L - 0.07f)));
    return fmaf(L, s, (1.0f - s) * 0.05f);
}

__global__ __launch_bounds__(BLOCK) void crazyleg_kernel(
    const float* __restrict__ q,
    const float* __restrict__ qd,
    const float* __restrict__ A,
    const float* __restrict__ U,
    float* __restrict__ out,
    int B)
{
    __shared__ float sR[BLOCK * 14];   // Rmat staging, flat row-major
    __shared__ float sL[BLOCK * 7];    // L staging, flat row-major

    const int t  = threadIdx.x;
    const int r0 = blockIdx.x * BLOCK;     // first row of this block
    const int i  = r0 + t;
    const size_t Bs = (size_t)B;

    // ---------------- phase A: Adot as a flat coalesced float4 stream -------
    // Adot = (U - A) / 0.12 over 7*B contiguous floats.
    {
        const float inv_t = 8.33333333333333f;
        const long long total = 7LL * B;
        const long long nf4   = total >> 2;           // float4 count
        const float4* U4 = reinterpret_cast<const float4*>(U);
        const float4* A4 = reinterpret_cast<const float4*>(A);
        float4* ad4 = reinterpret_cast<float4*>(out + 31 * Bs);
        const long long gtid   = (long long)blockIdx.x * BLOCK + t;
        const long long stride = (long long)gridDim.x * BLOCK;
        for (long long j = gtid; j < nf4; j += stride) {
            float4 u = U4[j], a = A4[j];
            float4 r;
            r.x = (u.x - a.x) * inv_t;
            r.y = (u.y - a.y) * inv_t;
            r.z = (u.z - a.z) * inv_t;
            r.w = (u.w - a.w) * inv_t;
            ad4[j] = r;
        }
        // scalar tail (total not divisible by 4)
        for (long long j = (nf4 << 2) + gtid; j < total; j += stride) {
            out[31 * Bs + j] = (U[j] - A[j]) * inv_t;
        }
    }

    // ---------------- phase B: per-row physics --------------------------
    if (i < B) {
        const float2 qv  = reinterpret_cast<const float2*>(q)[i];
        const float2 qdv = reinterpret_cast<const float2*>(qd)[i];
        const float q0 = qv.x, q1 = qv.y;
        const float qd0 = qdv.x, qd1 = qdv.y;

        float s0, c0, s1, c1;
        __sincosf(q0, &s0, &c0);
        __sincosf(q1, &s1, &c1);

        // ---- Gq ----
        // -(9.1*.15 + 5.1*.39)*9.81 = -32.90274 ; -(3.6*.2 + 1.5*.43)*9.81 = -13.39065
        const float g1 = -32.90274f * s0;
        const float g2 = -13.39065f * s1;
        reinterpret_cast<float2*>(out)[i] = make_float2(g1, g2);

        // ---- Cmat ----  k_c = 3.6*0.39*0.2 + 1.5*0.39*0.43 = 0.53235
        const float kc = 0.53235f;
        const float s01 = s0 * c1 - c0 * s1;      // sin(q0-q1)
        const float c01 = c0 * c1 + s0 * s1;      // cos(q0-q1)
        const float c12 = -kc * s01 * qd1;
        const float c21 =  kc * s01 * qd0;
        reinterpret_cast<float4*>(out + 2 * Bs)[i] =
            make_float4(0.0f, c12, c21, 0.0f);

        // ---- Mmat ----
        // m11 = 0.112007 + 9.1*0.0225 + 5.1*0.1521 = 1.092467
        // m22 = 0.0591636 + 3.6*0.04 + 1.5*0.1849 = 0.4805136
        const float m12 = kc * c01;
        reinterpret_cast<float4*>(out + 6 * Bs)[i] =
            make_float4(1.092467f, m12, m12, 0.4805136f);

        // ---- Rmat (stage to smem, flat layout row*14 + k) ----
        const float RVlat    =  0.05f  * __cosf(0.80f * (q1 - 1.74532925f)); // rad(100)
        const float RBF      = -0.038f * __cosf(q1 - 1.13446401f);           // rad(65)
        const float RRF_hip  =  0.053f * __cosf(q0 - 2.21656815f);           // rad(127)
        const float RRF_knee =  0.053f * __cosf(0.55f * (q1 - 1.74532925f));
        const float RST_hip  = -0.07f  * __cosf(q0 - 2.12930169f);           // rad(122)
        const float RST_knee = -0.04f  * __cosf(q1 - 1.48352986f);           // rad(85)
        const float RIl      =  0.045f * __cosf(0.60f * (q0 - 2.44346095f)); // rad(140)
        const float RGM      = -0.06f  * __cosf(0.75f * (q0 - PI_2f));       // rad(90)
        const float RMG      = -0.038f * __cosf(0.70f * (q1 - 0.87266463f)); // rad(50)

        float* r = &sR[t * 14];
        r[0]  = RIl;      r[1]  = RGM;      r[2]  = RRF_hip;  r[3]  = RST_hip;
        r[4]  = 0.0f;     r[5]  = 0.0f;     r[6]  = 0.0f;
        r[7]  = 0.0f;     r[8]  = 0.0f;     r[9]  = RRF_knee; r[10] = RST_knee;
        r[11] = RVlat;    r[12] = RBF;      r[13] = RMG;

        // ---- L (stage to smem, flat layout row*7 + k) ----
        const float dq0 = q0 - PI_2f;
        const float dk  = q1 - q0;
        float* lp = &sL[t * 7];
        lp[0] = blend(0.094f - 0.035f * dq0);
        lp[1] = blend(0.127f + 0.04f  * dq0);
        // base = sqrt(0.39^2 + 0.03^2) = 0.3911521698...
        lp[2] = blend(0.06f + sqrtf(fmaf(0.0234f, c0, 0.153f))
                      - 0.39115217f - 0.03f * dk);
        lp[3] = blend(0.055f + 0.05f * dq0 + 0.03f * dk);
        lp[4] = blend(0.046f - 0.03f * dk);
        lp[5] = blend(0.139f + 0.03f * dk);
        lp[6] = blend(0.055f + 0.03f * dk);
    }

    __syncthreads();

    // ---------------- phase C: coalesced flush of staged regions ------------
    const int n_rows = min(BLOCK, B - r0);
    // Rmat region: out + 10*B + 14*r0, n_rows*14 contiguous floats
    {
        float* dst = out + 10 * Bs + 14 * (size_t)r0;
        const int n = n_rows * 14;
        for (int j = t; j < n; j += BLOCK) dst[j] = sR[j];
    }
    // L region: out + 24*B + 7*r0, n_rows*7 contiguous floats
    {
        float* dst = out + 24 * Bs + 7 * (size_t)r0;
        const int n = n_rows * 7;
        for (int j = t; j < n; j += BLOCK) dst[j] = sL[j];
    }
}

extern "C" void kernel_launch(void* const* d_in, const int* in_sizes, int n_in,
                              void* d_out, int out_size)
{
    const float* q  = (const float*)d_in[0];
    const float* qd = (const float*)d_in[1];
    const float* A  = (const float*)d_in[2];
    const float* U  = (const float*)d_in[3];
    float* out = (float*)d_out;
    int B = in_sizes[0] / 2;
    int blocks = (B + BLOCK - 1) / BLOCK;
    crazyleg_kernel<<<blocks, BLOCK>>>(q, qd, A, U, out, B);
}